// round 8
// baseline (speedup 1.0000x reference)
#include <cuda_runtime.h>
#include <math.h>

#define NB   4
#define NTOK 65536
#define CD   256
#define LD   64
#define SD   64
#define AD   16
#define TT   64
#define BPB  74
#define NTILE 1024
#define PC 260
#define PL 68

typedef unsigned long long ull;

__device__ float g_w[(size_t)NB * NTOK * SD];   // softmax assignment weights
__device__ float g_M[NB * SD * LD];             // accumulated w^T @ shared
__device__ float g_wsum[NB * SD];
__device__ float g_st[NB * SD * CD];

__device__ __forceinline__ float geluf(float x) {
    return 0.5f * x * (1.0f + erff(x * 0.70710678118654752f));
}

#define FMAX2(d, a, b) asm("fma.rn.f32x2 %0, %1, %2, %0;" : "+l"(d) : "l"(a), "l"(b))

__device__ __forceinline__ float redx2(ull v) {
    return __uint_as_float((unsigned)v) + __uint_as_float((unsigned)(v >> 32));
}

// ---- packed f32x2 micro-kernel: thread (tr,tc) owns rows tr+16i, cols tc*4+j ----
// A row-major, pitch ald (must be even). Bi: k-pair interleaved, pitch 128 floats:
// Bi[k2*128 + c*2 + 0/1] = B[2*k2 + 0/1][c]. Accumulates packed; reduce with redx2.
__device__ __forceinline__ void mmx2(const float* __restrict__ A, int ald,
                                     const float* __restrict__ Bi,
                                     int tr, int tc, ull (&acc)[4][4])
{
#pragma unroll 4
    for (int k2 = 0; k2 < 32; k2++) {
        ulonglong2 p0 = *reinterpret_cast<const ulonglong2*>(Bi + k2 * 128 + tc * 8);
        ulonglong2 p1 = *reinterpret_cast<const ulonglong2*>(Bi + k2 * 128 + tc * 8 + 4);
        ull b[4] = { p0.x, p0.y, p1.x, p1.y };
        ull a[4];
#pragma unroll
        for (int i = 0; i < 4; i++)
            a[i] = *reinterpret_cast<const ull*>(A + (tr + 16 * i) * ald + 2 * k2);
#pragma unroll
        for (int i = 0; i < 4; i++)
#pragma unroll
            for (int j = 0; j < 4; j++) FMAX2(acc[i][j], a[i], b[j]);
    }
}

// stage a 64x64 row-major chunk (ld sld) into k-pair interleaved layout (pitch 128).
// Each thread reads two rows at c4 and writes two STS.128 — conflict-free.
__device__ __forceinline__ void stage64i(float* dst, const float* __restrict__ src,
                                         int sld, int tid)
{
    for (int i = tid; i < 512; i += 256) {
        int r2 = i >> 4, c4 = (i & 15) * 4;
        float4 v0 = *reinterpret_cast<const float4*>(src + (2 * r2) * sld + c4);
        float4 v1 = *reinterpret_cast<const float4*>(src + (2 * r2 + 1) * sld + c4);
        float* d = dst + r2 * 128 + c4 * 2;
        *reinterpret_cast<float4*>(d)     = make_float4(v0.x, v1.x, v0.y, v1.y);
        *reinterpret_cast<float4*>(d + 4) = make_float4(v0.z, v1.z, v0.w, v1.w);
    }
}

// ---------- scalar micro-kernels (k2 + GEMM4') ----------
__device__ __forceinline__ void mm64(const float* __restrict__ A, int ald,
                                     const float* __restrict__ B, int bld,
                                     int tr, int tc, float (&acc)[4][4])
{
#pragma unroll 8
    for (int kk = 0; kk < 64; kk++) {
        float4 b4 = *reinterpret_cast<const float4*>(B + kk * bld + tc * 4);
        float a[4] = { A[tr * ald + kk], A[(tr + 16) * ald + kk],
                       A[(tr + 32) * ald + kk], A[(tr + 48) * ald + kk] };
        float bb[4] = { b4.x, b4.y, b4.z, b4.w };
#pragma unroll
        for (int i = 0; i < 4; i++)
#pragma unroll
            for (int j = 0; j < 4; j++) acc[i][j] = fmaf(a[i], bb[j], acc[i][j]);
    }
}

__device__ __forceinline__ void mmT64(const float* __restrict__ A, int ald,
                                      const float* __restrict__ B, int bld,
                                      int tr, int tc, float (&acc)[4][4])
{
#pragma unroll 8
    for (int kk = 0; kk < 64; kk++) {
        float4 b4 = *reinterpret_cast<const float4*>(B + kk * bld + tc * 4);
        float a[4] = { A[kk * ald + tr], A[kk * ald + tr + 16],
                       A[kk * ald + tr + 32], A[kk * ald + tr + 48] };
        float bb[4] = { b4.x, b4.y, b4.z, b4.w };
#pragma unroll
        for (int i = 0; i < 4; i++)
#pragma unroll
            for (int j = 0; j < 4; j++) acc[i][j] = fmaf(a[i], bb[j], acc[i][j]);
    }
}

__device__ __forceinline__ void stage64c(float* dst, const float* __restrict__ src,
                                         int sld, int tid)
{
    for (int i = tid; i < 1024; i += 256) {
        int r = i >> 4, c4 = (i & 15) * 4;
        *reinterpret_cast<float4*>(dst + r * PL + c4) =
            *reinterpret_cast<const float4*>(src + r * sld + c4);
    }
}

__device__ __forceinline__ void ln64(const float* src, float* dst,
                                     const float* __restrict__ gg, const float* __restrict__ bb,
                                     int warp, int lane)
{
#pragma unroll 1
    for (int q = 0; q < 8; q++) {
        int s = warp * 8 + q;
        float v0 = src[s * PL + lane], v1 = src[s * PL + lane + 32];
        float s1 = v0 + v1, s2 = v0 * v0 + v1 * v1;
#pragma unroll
        for (int o = 16; o > 0; o >>= 1) {
            s1 += __shfl_xor_sync(~0u, s1, o);
            s2 += __shfl_xor_sync(~0u, s2, o);
        }
        float m = s1 * (1.0f / 64.0f);
        float r = rsqrtf(fmaxf(s2 * (1.0f / 64.0f) - m * m, 0.0f) + 1e-5f);
        dst[s * PL + lane]      = (v0 - m) * r * gg[lane] + bb[lane];
        dst[s * PL + lane + 32] = (v1 - m) * r * gg[lane + 32] + bb[lane + 32];
    }
}

// ============================ K1: phase 1 (f32x2 GEMMs, 2 CTAs/SM) ============================
extern "C" __global__ void __launch_bounds__(256, 2)
k1(const float* __restrict__ xg, const float* __restrict__ geo,
   const float* __restrict__ g1, const float* __restrict__ b1,
   const float* __restrict__ Wsh, const float* __restrict__ bsh,
   const float* __restrict__ Wasn, const float* __restrict__ basn)
{
    extern __shared__ float sm[];
    float* sX   = sm;                 // 64 x PL  (normalized x chunk)
    float* sSh  = sX + 64 * PL;       // 64 x PL  (shared)
    float* sLg  = sSh + 64 * PL;      // 64 x PL  (logits -> w)
    float* sGeo = sLg + 64 * PL;      // 64 x PL
    float* sW   = sGeo + 64 * PL;     // 64 x PL  (interleaved weight stage: 32x128)
    float* sG1  = sW + 64 * PL;       // 256
    float* sB1  = sG1 + 256;          // 256
    float* sMean = sB1 + 256;         // 64
    float* sRstd = sMean + 64;        // 64
    float* sBsh = sRstd + 64;         // 64
    float* sBa  = sBsh + 64;          // 64

    const int tid = threadIdx.x;
    const int tr = tid >> 4, tc = tid & 15;
    const int warp = tid >> 5, lane = tid & 31;
    const int b = blockIdx.x / BPB, rb = blockIdx.x % BPB;

    sG1[tid] = g1[tid]; sB1[tid] = b1[tid];
    if (tid < 64) { sBsh[tid] = bsh[tid]; sBa[tid] = basn[tid]; }
    float wloc = 0.0f;
    float Macc[4][4] = {};
    __syncthreads();

    for (int tile = rb; tile < NTILE; tile += BPB) {
        const size_t tok0 = (size_t)b * NTOK + (size_t)tile * TT;

        // pass 1: LN stats per row
#pragma unroll 1
        for (int q = 0; q < 8; q++) {
            int t = warp * 8 + q;
            const float* row = xg + (tok0 + t) * CD;
            float s1 = 0.0f, s2 = 0.0f;
#pragma unroll
            for (int k = 0; k < 8; k++) { float v = row[lane + 32 * k]; s1 += v; s2 += v * v; }
#pragma unroll
            for (int o = 16; o > 0; o >>= 1) {
                s1 += __shfl_xor_sync(~0u, s1, o);
                s2 += __shfl_xor_sync(~0u, s2, o);
            }
            if (lane == 0) {
                float m = s1 * (1.0f / 256.0f);
                sMean[t] = m;
                sRstd[t] = rsqrtf(fmaxf(s2 * (1.0f / 256.0f) - m * m, 0.0f) + 1e-5f);
            }
        }
        for (int i = tid; i < 64 * 64; i += 256) {
            int t = i >> 6, s = i & 63;
            sGeo[t * PL + s] = geo[(tok0 + t) * LD + s];
        }

        // GEMM1: shared = LN(x) @ Wsh  (K=256, chunked, packed)
        ull a1[4][4] = {};
        for (int kt = 0; kt < 4; kt++) {
            __syncthreads();
            const int base = kt * 64;
#pragma unroll
            for (int ii = 0; ii < 4; ii++) {
                int idx = tid + ii * 256;
                int r = idx >> 4, c4 = (idx & 15) * 4;
                float4 xv = *reinterpret_cast<const float4*>(xg + (tok0 + r) * CD + base + c4);
                float m = sMean[r], rs = sRstd[r];
                float4 o;
                o.x = (xv.x - m) * rs * sG1[base + c4 + 0] + sB1[base + c4 + 0];
                o.y = (xv.y - m) * rs * sG1[base + c4 + 1] + sB1[base + c4 + 1];
                o.z = (xv.z - m) * rs * sG1[base + c4 + 2] + sB1[base + c4 + 2];
                o.w = (xv.w - m) * rs * sG1[base + c4 + 3] + sB1[base + c4 + 3];
                *reinterpret_cast<float4*>(sX + r * PL + c4) = o;
            }
            stage64i(sW, Wsh + base * 64, 64, tid);
            __syncthreads();
            mmx2(sX, PL, sW, tr, tc, a1);
        }
        __syncthreads();
#pragma unroll
        for (int i = 0; i < 4; i++)
#pragma unroll
            for (int j = 0; j < 4; j++)
                sSh[(tr + 16 * i) * PL + tc * 4 + j] = redx2(a1[i][j]) + sBsh[tc * 4 + j];
        stage64i(sW, Wasn, 64, tid);
        __syncthreads();

        // GEMM3: logits = [shared|geo] @ Wasn  (K=128, packed)
        ull a3[4][4] = {};
        mmx2(sSh, PL, sW, tr, tc, a3);
        __syncthreads();
        stage64i(sW, Wasn + 64 * 64, 64, tid);
        __syncthreads();
        mmx2(sGeo, PL, sW, tr, tc, a3);
#pragma unroll
        for (int i = 0; i < 4; i++)
#pragma unroll
            for (int j = 0; j < 4; j++)
                sLg[(tr + 16 * i) * PL + tc * 4 + j] = redx2(a3[i][j]) + sBa[tc * 4 + j];
        __syncthreads();

        // softmax rows -> w
#pragma unroll 1
        for (int q = 0; q < 8; q++) {
            int t = warp * 8 + q;
            float v0 = sLg[t * PL + lane], v1 = sLg[t * PL + lane + 32];
            float mx = fmaxf(v0, v1);
#pragma unroll
            for (int o = 16; o > 0; o >>= 1) mx = fmaxf(mx, __shfl_xor_sync(~0u, mx, o));
            float e0 = __expf(v0 - mx), e1 = __expf(v1 - mx), ss = e0 + e1;
#pragma unroll
            for (int o = 16; o > 0; o >>= 1) ss += __shfl_xor_sync(~0u, ss, o);
            float inv = 1.0f / ss;
            float w0 = e0 * inv, w1 = e1 * inv;
            sLg[t * PL + lane] = w0; sLg[t * PL + lane + 32] = w1;
            float* wo = g_w + (tok0 + t) * SD;
            wo[lane] = w0; wo[lane + 32] = w1;
        }
        __syncthreads();

        if (tid < 64) {
            float cs = 0.0f;
            for (int t = 0; t < 64; t++) cs += sLg[t * PL + tid];
            wloc += cs;
        }

        // GEMM4': Macc += w^T @ shared (scalar, register resident)
        mmT64(sLg, PL, sSh, PL, tr, tc, Macc);
        __syncthreads();
    }

    if (tid < 64) atomicAdd(&g_wsum[b * 64 + tid], wloc);
#pragma unroll
    for (int i = 0; i < 4; i++)
#pragma unroll
        for (int j = 0; j < 4; j++)
            atomicAdd(&g_M[b * 4096 + (tr + 16 * i) * 64 + tc * 4 + j], Macc[i][j]);
}

// ============================ K2: slice reconstruction + latent transition ============================
extern "C" __global__ void __launch_bounds__(256, 1)
k2(const float* __restrict__ Wfe, const float* __restrict__ bfe,
   const float* __restrict__ Wd, const float* __restrict__ bd,
   const float* __restrict__ gdn, const float* __restrict__ bdn,
   const float* __restrict__ Wanc, const float* __restrict__ banc,
   const float* __restrict__ Wself, const float* __restrict__ Wctx,
   const float* __restrict__ gon, const float* __restrict__ bon,
   const float* __restrict__ Wup, const float* __restrict__ bup)
{
    extern __shared__ float sm[];
    float* sS  = sm;               // 64 x PC
    float* sWb = sS + 64 * PC;     // 256 x PL
    float* sT1 = sWb + 256 * PL;   // 64 x PL
    float* sT2 = sT1 + 64 * PL;    // 64 x PL
    float* sCx = sT2 + 64 * PL;    // 64 x PL
    float* sAn = sCx + 64 * PL;    // 16 x PL
    float* sAw = sAn + 16 * PL;    // 64 x 20
    float* sAs = sAw + 64 * 20;    // 16
    float* sWm = sAs + 16;         // 64

    const int tid = threadIdx.x;
    const int tr = tid >> 4, tc = tid & 15;
    const int warp = tid >> 5, lane = tid & 31;
    const int b = blockIdx.x;

    if (tid < 64) sWm[tid] = fmaxf(g_wsum[b * 64 + tid], 1e-6f);
    for (int i = tid; i < 64 * 64; i += 256) {
        int s = i >> 6, l = i & 63;
        sT1[s * PL + l] = g_M[b * 4096 + i];
    }
    __syncthreads();

    for (int cc = 0; cc < 4; cc++) {
        __syncthreads();
        stage64c(sWb, Wfe + cc * 64, 256, tid);
        __syncthreads();
        float acc[4][4] = {};
        mm64(sT1, PL, sWb, PL, tr, tc, acc);
#pragma unroll
        for (int i = 0; i < 4; i++)
#pragma unroll
            for (int j = 0; j < 4; j++) {
                int s = tr + 16 * i, c = cc * 64 + tc * 4 + j;
                float ws = sWm[s];
                sS[s * PC + c] = (acc[i][j] + ws * bfe[c]) / ws;
            }
    }
    __syncthreads();

    for (int i = tid; i < 256 * 16; i += 256) {
        int r = i >> 4, c4 = (i & 15) * 4;
        *reinterpret_cast<float4*>(sWb + r * PL + c4) =
            *reinterpret_cast<const float4*>(Wd + r * 64 + c4);
    }
    __syncthreads();
    {
        float acc[4][4] = {};
        for (int kt = 0; kt < 4; kt++)
            mm64(sS + kt * 64, PC, sWb + kt * 64 * PL, PL, tr, tc, acc);
        __syncthreads();
#pragma unroll
        for (int i = 0; i < 4; i++)
#pragma unroll
            for (int j = 0; j < 4; j++) {
                int c = tc * 4 + j;
                sT2[(tr + 16 * i) * PL + c] = acc[i][j] + bd[c];
            }
    }
    __syncthreads();
    ln64(sT2, sT1, gdn, bdn, warp, lane);
    __syncthreads();

    {
        int s = tid >> 2, a0 = (tid & 3) * 4;
        float a4[4] = {0.f, 0.f, 0.f, 0.f};
        for (int k = 0; k < 64; k++) {
            float av = sT1[s * PL + k];
#pragma unroll
            for (int j = 0; j < 4; j++) a4[j] = fmaf(av, Wanc[k * 16 + a0 + j], a4[j]);
        }
#pragma unroll
        for (int j = 0; j < 4; j++) sAw[s * 20 + a0 + j] = a4[j] + banc[a0 + j];
    }
    __syncthreads();
    if (tid < 64) {
        float mx = -1e30f;
        for (int a = 0; a < 16; a++) mx = fmaxf(mx, sAw[tid * 20 + a]);
        float e[16], ss = 0.0f;
        for (int a = 0; a < 16; a++) { e[a] = __expf(sAw[tid * 20 + a] - mx); ss += e[a]; }
        float inv = 1.0f / ss;
        for (int a = 0; a < 16; a++) sAw[tid * 20 + a] = e[a] * inv;
    }
    __syncthreads();
    if (tid < 16) {
        float cs = 0.0f;
        for (int s = 0; s < 64; s++) cs += sAw[s * 20 + tid];
        sAs[tid] = fmaxf(cs, 1e-6f);
    }
    __syncthreads();
    for (int idx = tid; idx < 16 * 64; idx += 256) {
        int a = idx >> 6, d = idx & 63;
        float s = 0.0f;
        for (int t = 0; t < 64; t++) s = fmaf(sAw[t * 20 + a], sT1[t * PL + d], s);
        sAn[a * PL + d] = s / sAs[a];
    }
    __syncthreads();
    for (int idx = tid; idx < 64 * 64; idx += 256) {
        int s = idx >> 6, d = idx & 63;
        float v = 0.0f;
#pragma unroll
        for (int a = 0; a < 16; a++) v = fmaf(sAw[s * 20 + a], sAn[a * PL + d], v);
        sCx[s * PL + d] = v;
    }
    __syncthreads();

    {
        float acc[4][4] = {};
        for (int i = tid; i < 64 * 16; i += 256) {
            int r = i >> 4, c4 = (i & 15) * 4;
            *reinterpret_cast<float4*>(sWb + r * PL + c4) =
                *reinterpret_cast<const float4*>(Wself + r * 64 + c4);
        }
        __syncthreads();
        mm64(sT1, PL, sWb, PL, tr, tc, acc);
        __syncthreads();
        for (int i = tid; i < 64 * 16; i += 256) {
            int r = i >> 4, c4 = (i & 15) * 4;
            *reinterpret_cast<float4*>(sWb + r * PL + c4) =
                *reinterpret_cast<const float4*>(Wctx + r * 64 + c4);
        }
        __syncthreads();
        mm64(sCx, PL, sWb, PL, tr, tc, acc);
#pragma unroll
        for (int i = 0; i < 4; i++)
#pragma unroll
            for (int j = 0; j < 4; j++) {
                int row = tr + 16 * i, c = tc * 4 + j;
                sT2[row * PL + c] = sT1[row * PL + c] + geluf(acc[i][j]);
            }
    }
    __syncthreads();
    ln64(sT2, sCx, gon, bon, warp, lane);
    __syncthreads();

    for (int cc = 0; cc < 4; cc++) {
        __syncthreads();
        for (int i = tid; i < 64 * 16; i += 256) {
            int r = i >> 4, c4 = (i & 15) * 4;
            *reinterpret_cast<float4*>(sWb + r * PL + c4) =
                *reinterpret_cast<const float4*>(Wup + r * 256 + cc * 64 + c4);
        }
        __syncthreads();
        float acc[4][4] = {};
        mm64(sCx, PL, sWb, PL, tr, tc, acc);
#pragma unroll
        for (int i = 0; i < 4; i++)
#pragma unroll
            for (int j = 0; j < 4; j++) {
                int row = tr + 16 * i, c = cc * 64 + tc * 4 + j;
                g_st[b * 16384 + row * 256 + c] = acc[i][j] + bup[c];
            }
    }
}

// ============================ K3: reader + channel mixer (f32x2, 2 CTAs/SM) ============================
extern "C" __global__ void __launch_bounds__(256, 2)
k3(const float* __restrict__ xg,
   const float* __restrict__ g2, const float* __restrict__ b2,
   const float* __restrict__ Win, const float* __restrict__ binp,
   const float* __restrict__ Wout, const float* __restrict__ boutp,
   float* __restrict__ out)
{
    extern __shared__ float sm[];
    float* sH  = sm;               // 64 x PC : LN2(y)
    float* sWt = sH + 64 * PC;     // 64 x PL : w tile -> v half -> act
    float* sWs = sWt + 64 * PL;    // 64 x PL : interleaved stage (32x128)
    float* sG2 = sWs + 64 * PL;    // 256
    float* sB2 = sG2 + 256;        // 256
    float* sBi = sB2 + 256;        // 128

    const int tid = threadIdx.x;
    const int tr = tid >> 4, tc = tid & 15;
    const int warp = tid >> 5, lane = tid & 31;
    const int b = blockIdx.x / BPB, rb = blockIdx.x % BPB;

    sG2[tid] = g2[tid]; sB2[tid] = b2[tid];
    if (tid < 128) sBi[tid] = binp[tid];
    __syncthreads();

    for (int tile = rb; tile < NTILE; tile += BPB) {
        const size_t tok0 = (size_t)b * NTOK + (size_t)tile * TT;
        __syncthreads();

        // load w tile -> sWt
        for (int i = tid; i < 64 * 64; i += 256) {
            int t = i >> 6, s = i & 63;
            sWt[t * PL + s] = g_w[(tok0 + t) * SD + s];
        }

        // y = x + w@st (st chunks staged interleaved)
        for (int cc = 0; cc < 4; cc++) {
            __syncthreads();
            stage64i(sWs, g_st + b * 16384 + cc * 64, 256, tid);
            __syncthreads();
            ull ay[4][4] = {};
            mmx2(sWt, PL, sWs, tr, tc, ay);
#pragma unroll
            for (int i = 0; i < 4; i++) {
                int row = tr + 16 * i, c = cc * 64 + tc * 4;
                float4 xv = *reinterpret_cast<const float4*>(xg + (tok0 + row) * CD + c);
                float4 yv = make_float4(redx2(ay[i][0]) + xv.x, redx2(ay[i][1]) + xv.y,
                                        redx2(ay[i][2]) + xv.z, redx2(ay[i][3]) + xv.w);
                *reinterpret_cast<float4*>(out + (tok0 + row) * CD + c) = yv;
            }
        }
        __syncthreads();

        // LN2: read y from out, h -> sH
#pragma unroll 1
        for (int q = 0; q < 8; q++) {
            int t = warp * 8 + q;
            const float* yrow = out + (tok0 + t) * CD;
            float v[8], s1 = 0.0f, s2 = 0.0f;
#pragma unroll
            for (int k = 0; k < 8; k++) { v[k] = yrow[lane + 32 * k]; s1 += v[k]; s2 += v[k] * v[k]; }
#pragma unroll
            for (int o = 16; o > 0; o >>= 1) {
                s1 += __shfl_xor_sync(~0u, s1, o);
                s2 += __shfl_xor_sync(~0u, s2, o);
            }
            float m = s1 * (1.0f / 256.0f);
            float r = rsqrtf(fmaxf(s2 * (1.0f / 256.0f) - m * m, 0.0f) + 1e-5f);
#pragma unroll
            for (int k = 0; k < 8; k++) {
                int c = lane + 32 * k;
                sH[t * PC + c] = (v[k] - m) * r * sG2[c] + sB2[c];
            }
        }

        // Win half 0 (v): acc packed, result -> sWt (w-tile no longer needed)
        {
            ull acch[4][4] = {};
            for (int kt = 0; kt < 4; kt++) {
                __syncthreads();   // kt=0: sH visible + sWt reads (w@st) long done
                stage64i(sWs, Win + kt * 64 * 128, 128, tid);
                __syncthreads();
                mmx2(sH + kt * 64, PC, sWs, tr, tc, acch);
            }
#pragma unroll
            for (int i = 0; i < 4; i++)
#pragma unroll
                for (int j = 0; j < 4; j++) {
                    int c = tc * 4 + j;
                    sWt[(tr + 16 * i) * PL + c] = redx2(acch[i][j]) + sBi[c];
                }
        }
        // Win half 1 (g) + activation
        {
            ull accg[4][4] = {};
            for (int kt = 0; kt < 4; kt++) {
                __syncthreads();
                stage64i(sWs, Win + kt * 64 * 128 + 64, 128, tid);
                __syncthreads();
                mmx2(sH + kt * 64, PC, sWs, tr, tc, accg);
            }
#pragma unroll
            for (int i = 0; i < 4; i++)
#pragma unroll
                for (int j = 0; j < 4; j++) {
                    int c = tc * 4 + j;
                    int slot = (tr + 16 * i) * PL + c;
                    float v = sWt[slot];   // own write from half 0
                    float gg = redx2(accg[i][j]) + sBi[64 + c];
                    sWt[slot] = geluf(v) * (1.0f / (1.0f + __expf(-gg)));
                }
        }

        // out = y + act @ Wout + bout
        for (int cc = 0; cc < 4; cc++) {
            __syncthreads();   // cc=0: act writes visible before mm reads sWt
            stage64i(sWs, Wout + cc * 64, 256, tid);
            __syncthreads();
            ull ao[4][4] = {};
            mmx2(sWt, PL, sWs, tr, tc, ao);
#pragma unroll
            for (int i = 0; i < 4; i++) {
                int row = tr + 16 * i, c = cc * 64 + tc * 4;
                float4 yv = *reinterpret_cast<const float4*>(out + (tok0 + row) * CD + c);
                float4 bo = *reinterpret_cast<const float4*>(boutp + c);
                float4 ov = make_float4(yv.x + redx2(ao[i][0]) + bo.x,
                                        yv.y + redx2(ao[i][1]) + bo.y,
                                        yv.z + redx2(ao[i][2]) + bo.z,
                                        yv.w + redx2(ao[i][3]) + bo.w);
                *reinterpret_cast<float4*>(out + (tok0 + row) * CD + c) = ov;
            }
        }
    }
}

// ============================ launcher ============================
extern "C" void kernel_launch(void* const* d_in, const int* in_sizes, int n_in,
                              void* d_out, int out_size)
{
    const float* x     = (const float*)d_in[0];
    const float* geo   = (const float*)d_in[1];
    const float* ln1g  = (const float*)d_in[2];
    const float* ln1b  = (const float*)d_in[3];
    const float* Wsh   = (const float*)d_in[4];
    const float* bsh   = (const float*)d_in[5];
    const float* Wfe   = (const float*)d_in[6];
    const float* bfe   = (const float*)d_in[7];
    const float* Wasn  = (const float*)d_in[8];
    const float* basn  = (const float*)d_in[9];
    const float* Wd    = (const float*)d_in[10];
    const float* bd    = (const float*)d_in[11];
    const float* gdn   = (const float*)d_in[12];
    const float* bdn   = (const float*)d_in[13];
    const float* Wanc  = (const float*)d_in[14];
    const float* banc  = (const float*)d_in[15];
    const float* Wself = (const float*)d_in[16];
    const float* Wctx  = (const float*)d_in[17];
    const float* gon   = (const float*)d_in[18];
    const float* bon   = (const float*)d_in[19];
    const float* Wup   = (const float*)d_in[20];
    const float* bup   = (const float*)d_in[21];
    const float* ln2g  = (const float*)d_in[22];
    const float* ln2b  = (const float*)d_in[23];
    const float* Win   = (const float*)d_in[24];
    const float* binp  = (const float*)d_in[25];
    const float* Wout  = (const float*)d_in[26];
    const float* boutp = (const float*)d_in[27];
    float* out = (float*)d_out;

    const size_t S1 = (size_t)(5 * 64 * PL + 2 * 256 + 4 * 64) * sizeof(float);
    const size_t S2 = (size_t)(64 * PC + 256 * PL + 3 * 64 * PL + 16 * PL + 64 * 20 + 16 + 64) * sizeof(float);
    const size_t S3 = (size_t)(64 * PC + 2 * 64 * PL + 2 * 256 + 128) * sizeof(float);

    cudaFuncSetAttribute(k1, cudaFuncAttributeMaxDynamicSharedMemorySize, (int)S1);
    cudaFuncSetAttribute(k2, cudaFuncAttributeMaxDynamicSharedMemorySize, (int)S2);
    cudaFuncSetAttribute(k3, cudaFuncAttributeMaxDynamicSharedMemorySize, (int)S3);

    void* pM = nullptr; void* pwsum = nullptr;
    cudaGetSymbolAddress(&pM, g_M);
    cudaGetSymbolAddress(&pwsum, g_wsum);
    cudaMemsetAsync(pM, 0, (size_t)NB * SD * LD * sizeof(float), 0);
    cudaMemsetAsync(pwsum, 0, (size_t)NB * SD * sizeof(float), 0);

    k1<<<NB * BPB, 256, S1>>>(x, geo, ln1g, ln1b, Wsh, bsh, Wasn, basn);
    k2<<<NB, 256, S2>>>(Wfe, bfe, Wd, bd, gdn, bdn, Wanc, banc, Wself, Wctx, gon, bon, Wup, bup);
    k3<<<NB * BPB, 256, S3>>>(x, ln2g, ln2b, Win, binp, Wout, boutp, out);
}

// round 9
// speedup vs baseline: 1.5461x; 1.5461x over previous
#include <cuda_runtime.h>
#include <math.h>

#define NB   4
#define NTOK 65536
#define CD   256
#define LD   64
#define SD   64
#define TT   64
#define BPB  74
#define NTILE 1024
#define PH 260
#define PL 68

__device__ float g_w[(size_t)NB * NTOK * SD];   // softmax weights (tf32-rounded)
__device__ float g_M[NB * SD * LD];             // accumulated w^T @ shared
__device__ float g_wsum[NB * SD];
__device__ float g_st[NB * SD * CD];            // st (tf32-rounded)
__device__ float g_WinT[CD * 128];              // tf32-rounded Win
__device__ float g_WoutT[LD * CD];              // tf32-rounded Wout

__device__ __forceinline__ float geluf(float x) {
    return 0.5f * x * (1.0f + erff(x * 0.70710678118654752f));
}
__device__ __forceinline__ float sigm(float x) { return 1.0f / (1.0f + __expf(-x)); }

__device__ __forceinline__ float totf(float x) {
    unsigned r;
    asm("cvt.rna.tf32.f32 %0, %1;" : "=r"(r) : "f"(x));
    return __uint_as_float(r);
}

__device__ __forceinline__ void mma8(float (&d)[4], const unsigned (&a)[4], const unsigned (&b)[2]) {
    asm volatile("mma.sync.aligned.m16n8k8.row.col.f32.tf32.tf32.f32 "
                 "{%0,%1,%2,%3}, {%4,%5,%6,%7}, {%8,%9}, {%0,%1,%2,%3};"
                 : "+f"(d[0]), "+f"(d[1]), "+f"(d[2]), "+f"(d[3])
                 : "r"(a[0]), "r"(a[1]), "r"(a[2]), "r"(a[3]), "r"(b[0]), "r"(b[1]));
}

// warp-level: acc(16x32) += A(64xK=64 slice, lda) @ B(64x64 chunk, ld 68).
// warp tile: rows wr*16.., cols wc*32 + 8t. Operands must be tf32-rounded.
__device__ __forceinline__ void mma_warp64(const float* __restrict__ sA, int lda,
                                           const float* __restrict__ sB,
                                           int wr, int wc, int g, int q, float (&acc)[4][4])
{
#pragma unroll
    for (int k8 = 0; k8 < 64; k8 += 8) {
        const float* Ab = sA + (wr * 16 + g) * lda + k8 + q;
        unsigned a[4] = { __float_as_uint(Ab[0]),  __float_as_uint(Ab[8 * lda]),
                          __float_as_uint(Ab[4]),  __float_as_uint(Ab[8 * lda + 4]) };
#pragma unroll
        for (int t = 0; t < 4; t++) {
            const float* Bb = sB + (k8 + q) * PL + wc * 32 + t * 8 + g;
            unsigned b[2] = { __float_as_uint(Bb[0]), __float_as_uint(Bb[4 * PL]) };
            mma8(acc[t], a, b);
        }
    }
}

// ---------- scalar micro-kernels ----------
__device__ __forceinline__ void mm64(const float* __restrict__ A, int ald,
                                     const float* __restrict__ B, int bld,
                                     int tr, int tc, float (&acc)[4][4])
{
#pragma unroll 8
    for (int kk = 0; kk < 64; kk++) {
        float4 b4 = *reinterpret_cast<const float4*>(B + kk * bld + tc * 4);
        float a[4] = { A[tr * ald + kk], A[(tr + 16) * ald + kk],
                       A[(tr + 32) * ald + kk], A[(tr + 48) * ald + kk] };
        float bb[4] = { b4.x, b4.y, b4.z, b4.w };
#pragma unroll
        for (int i = 0; i < 4; i++)
#pragma unroll
            for (int j = 0; j < 4; j++) acc[i][j] = fmaf(a[i], bb[j], acc[i][j]);
    }
}

__device__ __forceinline__ void mmT64(const float* __restrict__ A, int ald,
                                      const float* __restrict__ B, int bld,
                                      int tr, int tc, float (&acc)[4][4])
{
#pragma unroll 8
    for (int kk = 0; kk < 64; kk++) {
        float4 b4 = *reinterpret_cast<const float4*>(B + kk * bld + tc * 4);
        float a[4] = { A[kk * ald + tr], A[kk * ald + tr + 16],
                       A[kk * ald + tr + 32], A[kk * ald + tr + 48] };
        float bb[4] = { b4.x, b4.y, b4.z, b4.w };
#pragma unroll
        for (int i = 0; i < 4; i++)
#pragma unroll
            for (int j = 0; j < 4; j++) acc[i][j] = fmaf(a[i], bb[j], acc[i][j]);
    }
}

__device__ __forceinline__ void stage64c(float* dst, const float* __restrict__ src,
                                         int sld, int tid)
{
    for (int i = tid; i < 1024; i += 256) {
        int r = i >> 4, c4 = (i & 15) * 4;
        *reinterpret_cast<float4*>(dst + r * PL + c4) =
            *reinterpret_cast<const float4*>(src + r * sld + c4);
    }
}

__device__ __forceinline__ void ln64(const float* src, float* dst,
                                     const float* __restrict__ gg, const float* __restrict__ bb,
                                     int warp, int lane)
{
#pragma unroll 1
    for (int q = 0; q < 8; q++) {
        int s = warp * 8 + q;
        float v0 = src[s * PL + lane], v1 = src[s * PL + lane + 32];
        float s1 = v0 + v1, s2 = v0 * v0 + v1 * v1;
#pragma unroll
        for (int o = 16; o > 0; o >>= 1) {
            s1 += __shfl_xor_sync(~0u, s1, o);
            s2 += __shfl_xor_sync(~0u, s2, o);
        }
        float m = s1 * (1.0f / 64.0f);
        float r = rsqrtf(fmaxf(s2 * (1.0f / 64.0f) - m * m, 0.0f) + 1e-5f);
        dst[s * PL + lane]      = (v0 - m) * r * gg[lane] + bb[lane];
        dst[s * PL + lane + 32] = (v1 - m) * r * gg[lane + 32] + bb[lane + 32];
    }
}

// ============================ K0: tf32-round the channel-mixer weights ============================
extern "C" __global__ void k0(const float* __restrict__ Win, const float* __restrict__ Wout)
{
    int i = blockIdx.x * 256 + threadIdx.x;
    if (i < CD * 128) g_WinT[i] = totf(Win[i]);
    if (i < LD * CD)  g_WoutT[i] = totf(Wout[i]);
}

// ============================ K1: phase 1 (scalar, 2 CTAs/SM — proven R6) ============================
extern "C" __global__ void __launch_bounds__(256, 2)
k1(const float* __restrict__ xg, const float* __restrict__ geo,
   const float* __restrict__ g1, const float* __restrict__ b1,
   const float* __restrict__ Wsh, const float* __restrict__ bsh,
   const float* __restrict__ Wasn, const float* __restrict__ basn)
{
    extern __shared__ float sm[];
    float* sX   = sm;                 // 64 x PL
    float* sSh  = sX + 64 * PL;       // 64 x PL
    float* sLg  = sSh + 64 * PL;      // 64 x PL
    float* sGeo = sLg + 64 * PL;      // 64 x PL
    float* sW   = sGeo + 64 * PL;     // 64 x PL
    float* sG1  = sW + 64 * PL;       // 256
    float* sB1  = sG1 + 256;          // 256
    float* sMean = sB1 + 256;         // 64
    float* sRstd = sMean + 64;        // 64
    float* sBsh = sRstd + 64;         // 64
    float* sBa  = sBsh + 64;          // 64

    const int tid = threadIdx.x;
    const int tr = tid >> 4, tc = tid & 15;
    const int warp = tid >> 5, lane = tid & 31;
    const int b = blockIdx.x / BPB, rb = blockIdx.x % BPB;

    sG1[tid] = g1[tid]; sB1[tid] = b1[tid];
    if (tid < 64) { sBsh[tid] = bsh[tid]; sBa[tid] = basn[tid]; }
    float wloc = 0.0f;
    float Macc[4][4] = {};
    __syncthreads();

    for (int tile = rb; tile < NTILE; tile += BPB) {
        const size_t tok0 = (size_t)b * NTOK + (size_t)tile * TT;

        // LN stats
#pragma unroll 1
        for (int q = 0; q < 8; q++) {
            int t = warp * 8 + q;
            const float* row = xg + (tok0 + t) * CD;
            float s1 = 0.0f, s2 = 0.0f;
#pragma unroll
            for (int k = 0; k < 8; k++) { float v = row[lane + 32 * k]; s1 += v; s2 += v * v; }
#pragma unroll
            for (int o = 16; o > 0; o >>= 1) {
                s1 += __shfl_xor_sync(~0u, s1, o);
                s2 += __shfl_xor_sync(~0u, s2, o);
            }
            if (lane == 0) {
                float m = s1 * (1.0f / 256.0f);
                sMean[t] = m;
                sRstd[t] = rsqrtf(fmaxf(s2 * (1.0f / 256.0f) - m * m, 0.0f) + 1e-5f);
            }
        }
        for (int i = tid; i < 64 * 64; i += 256) {
            int t = i >> 6, s = i & 63;
            sGeo[t * PL + s] = geo[(tok0 + t) * LD + s];
        }

        // GEMM1: shared = LN(x) @ Wsh
        float a1[4][4] = {};
        for (int kt = 0; kt < 4; kt++) {
            __syncthreads();
            const int base = kt * 64;
#pragma unroll
            for (int ii = 0; ii < 4; ii++) {
                int idx = tid + ii * 256;
                int r = idx >> 4, c4 = (idx & 15) * 4;
                float4 xv = *reinterpret_cast<const float4*>(xg + (tok0 + r) * CD + base + c4);
                float m = sMean[r], rs = sRstd[r];
                float4 o;
                o.x = (xv.x - m) * rs * sG1[base + c4 + 0] + sB1[base + c4 + 0];
                o.y = (xv.y - m) * rs * sG1[base + c4 + 1] + sB1[base + c4 + 1];
                o.z = (xv.z - m) * rs * sG1[base + c4 + 2] + sB1[base + c4 + 2];
                o.w = (xv.w - m) * rs * sG1[base + c4 + 3] + sB1[base + c4 + 3];
                *reinterpret_cast<float4*>(sX + r * PL + c4) = o;
            }
            stage64c(sW, Wsh + base * 64, 64, tid);
            __syncthreads();
            mm64(sX, PL, sW, PL, tr, tc, a1);
        }
        __syncthreads();
#pragma unroll
        for (int i = 0; i < 4; i++)
#pragma unroll
            for (int j = 0; j < 4; j++)
                sSh[(tr + 16 * i) * PL + tc * 4 + j] = a1[i][j] + sBsh[tc * 4 + j];
        stage64c(sW, Wasn, 64, tid);
        __syncthreads();

        // GEMM3: logits
        float a3[4][4] = {};
        mm64(sSh, PL, sW, PL, tr, tc, a3);
        __syncthreads();
        stage64c(sW, Wasn + 64 * 64, 64, tid);
        __syncthreads();
        mm64(sGeo, PL, sW, PL, tr, tc, a3);
#pragma unroll
        for (int i = 0; i < 4; i++)
#pragma unroll
            for (int j = 0; j < 4; j++)
                sLg[(tr + 16 * i) * PL + tc * 4 + j] = a3[i][j] + sBa[tc * 4 + j];
        __syncthreads();

        // softmax -> w (spill rounded to tf32 for k3's mma)
#pragma unroll 1
        for (int q = 0; q < 8; q++) {
            int t = warp * 8 + q;
            float v0 = sLg[t * PL + lane], v1 = sLg[t * PL + lane + 32];
            float mx = fmaxf(v0, v1);
#pragma unroll
            for (int o = 16; o > 0; o >>= 1) mx = fmaxf(mx, __shfl_xor_sync(~0u, mx, o));
            float e0 = __expf(v0 - mx), e1 = __expf(v1 - mx), ss = e0 + e1;
#pragma unroll
            for (int o = 16; o > 0; o >>= 1) ss += __shfl_xor_sync(~0u, ss, o);
            float inv = 1.0f / ss;
            float w0 = e0 * inv, w1 = e1 * inv;
            sLg[t * PL + lane] = w0; sLg[t * PL + lane + 32] = w1;
            float* wo = g_w + (tok0 + t) * SD;
            wo[lane] = totf(w0); wo[lane + 32] = totf(w1);
        }
        __syncthreads();

        if (tid < 64) {
            float cs = 0.0f;
            for (int t = 0; t < 64; t++) cs += sLg[t * PL + tid];
            wloc += cs;
        }
        mmT64(sLg, PL, sSh, PL, tr, tc, Macc);
        __syncthreads();
    }

    if (tid < 64) atomicAdd(&g_wsum[b * 64 + tid], wloc);
#pragma unroll
    for (int i = 0; i < 4; i++)
#pragma unroll
        for (int j = 0; j < 4; j++)
            atomicAdd(&g_M[b * 4096 + (tr + 16 * i) * 64 + tc * 4 + j], Macc[i][j]);
}

// ============================ K2: slice reconstruction + latent transition ============================
extern "C" __global__ void __launch_bounds__(256, 1)
k2(const float* __restrict__ Wfe, const float* __restrict__ bfe,
   const float* __restrict__ Wd, const float* __restrict__ bd,
   const float* __restrict__ gdn, const float* __restrict__ bdn,
   const float* __restrict__ Wanc, const float* __restrict__ banc,
   const float* __restrict__ Wself, const float* __restrict__ Wctx,
   const float* __restrict__ gon, const float* __restrict__ bon,
   const float* __restrict__ Wup, const float* __restrict__ bup)
{
    extern __shared__ float sm[];
    float* sS  = sm;               // 64 x PH
    float* sWb = sS + 64 * PH;     // 256 x PL
    float* sT1 = sWb + 256 * PL;   // 64 x PL
    float* sT2 = sT1 + 64 * PL;    // 64 x PL
    float* sCx = sT2 + 64 * PL;    // 64 x PL
    float* sAn = sCx + 64 * PL;    // 16 x PL
    float* sAw = sAn + 16 * PL;    // 64 x 20
    float* sAs = sAw + 64 * 20;    // 16
    float* sWm = sAs + 16;         // 64

    const int tid = threadIdx.x;
    const int tr = tid >> 4, tc = tid & 15;
    const int warp = tid >> 5, lane = tid & 31;
    const int b = blockIdx.x;

    if (tid < 64) sWm[tid] = fmaxf(g_wsum[b * 64 + tid], 1e-6f);
    for (int i = tid; i < 64 * 64; i += 256) {
        int s = i >> 6, l = i & 63;
        sT1[s * PL + l] = g_M[b * 4096 + i];
    }
    __syncthreads();

    for (int cc = 0; cc < 4; cc++) {
        __syncthreads();
        stage64c(sWb, Wfe + cc * 64, 256, tid);
        __syncthreads();
        float acc[4][4] = {};
        mm64(sT1, PL, sWb, PL, tr, tc, acc);
#pragma unroll
        for (int i = 0; i < 4; i++)
#pragma unroll
            for (int j = 0; j < 4; j++) {
                int s = tr + 16 * i, c = cc * 64 + tc * 4 + j;
                float ws = sWm[s];
                sS[s * PH + c] = (acc[i][j] + ws * bfe[c]) / ws;
            }
    }
    __syncthreads();

    for (int i = tid; i < 256 * 16; i += 256) {
        int r = i >> 4, c4 = (i & 15) * 4;
        *reinterpret_cast<float4*>(sWb + r * PL + c4) =
            *reinterpret_cast<const float4*>(Wd + r * 64 + c4);
    }
    __syncthreads();
    {
        float acc[4][4] = {};
        for (int kt = 0; kt < 4; kt++)
            mm64(sS + kt * 64, PH, sWb + kt * 64 * PL, PL, tr, tc, acc);
        __syncthreads();
#pragma unroll
        for (int i = 0; i < 4; i++)
#pragma unroll
            for (int j = 0; j < 4; j++) {
                int c = tc * 4 + j;
                sT2[(tr + 16 * i) * PL + c] = acc[i][j] + bd[c];
            }
    }
    __syncthreads();
    ln64(sT2, sT1, gdn, bdn, warp, lane);
    __syncthreads();

    {
        int s = tid >> 2, a0 = (tid & 3) * 4;
        float a4[4] = {0.f, 0.f, 0.f, 0.f};
        for (int k = 0; k < 64; k++) {
            float av = sT1[s * PL + k];
#pragma unroll
            for (int j = 0; j < 4; j++) a4[j] = fmaf(av, Wanc[k * 16 + a0 + j], a4[j]);
        }
#pragma unroll
        for (int j = 0; j < 4; j++) sAw[s * 20 + a0 + j] = a4[j] + banc[a0 + j];
    }
    __syncthreads();
    if (tid < 64) {
        float mx = -1e30f;
        for (int a = 0; a < 16; a++) mx = fmaxf(mx, sAw[tid * 20 + a]);
        float e[16], ss = 0.0f;
        for (int a = 0; a < 16; a++) { e[a] = __expf(sAw[tid * 20 + a] - mx); ss += e[a]; }
        float inv = 1.0f / ss;
        for (int a = 0; a < 16; a++) sAw[tid * 20 + a] = e[a] * inv;
    }
    __syncthreads();
    if (tid < 16) {
        float cs = 0.0f;
        for (int s = 0; s < 64; s++) cs += sAw[s * 20 + tid];
        sAs[tid] = fmaxf(cs, 1e-6f);
    }
    __syncthreads();
    for (int idx = tid; idx < 16 * 64; idx += 256) {
        int a = idx >> 6, d = idx & 63;
        float s = 0.0f;
        for (int t = 0; t < 64; t++) s = fmaf(sAw[t * 20 + a], sT1[t * PL + d], s);
        sAn[a * PL + d] = s / sAs[a];
    }
    __syncthreads();
    for (int idx = tid; idx < 64 * 64; idx += 256) {
        int s = idx >> 6, d = idx & 63;
        float v = 0.0f;
#pragma unroll
        for (int a = 0; a < 16; a++) v = fmaf(sAw[s * 20 + a], sAn[a * PL + d], v);
        sCx[s * PL + d] = v;
    }
    __syncthreads();

    {
        float acc[4][4] = {};
        for (int i = tid; i < 64 * 16; i += 256) {
            int r = i >> 4, c4 = (i & 15) * 4;
            *reinterpret_cast<float4*>(sWb + r * PL + c4) =
                *reinterpret_cast<const float4*>(Wself + r * 64 + c4);
        }
        __syncthreads();
        mm64(sT1, PL, sWb, PL, tr, tc, acc);
        __syncthreads();
        for (int i = tid; i < 64 * 16; i += 256) {
            int r = i >> 4, c4 = (i & 15) * 4;
            *reinterpret_cast<float4*>(sWb + r * PL + c4) =
                *reinterpret_cast<const float4*>(Wctx + r * 64 + c4);
        }
        __syncthreads();
        mm64(sCx, PL, sWb, PL, tr, tc, acc);
#pragma unroll
        for (int i = 0; i < 4; i++)
#pragma unroll
            for (int j = 0; j < 4; j++) {
                int row = tr + 16 * i, c = tc * 4 + j;
                sT2[row * PL + c] = sT1[row * PL + c] + geluf(acc[i][j]);
            }
    }
    __syncthreads();
    ln64(sT2, sCx, gon, bon, warp, lane);
    __syncthreads();

    // st = LN(ul)@Wup + bup  (stored tf32-rounded for k3 mma)
    for (int cc = 0; cc < 4; cc++) {
        __syncthreads();
        for (int i = tid; i < 64 * 16; i += 256) {
            int r = i >> 4, c4 = (i & 15) * 4;
            *reinterpret_cast<float4*>(sWb + r * PL + c4) =
                *reinterpret_cast<const float4*>(Wup + r * 256 + cc * 64 + c4);
        }
        __syncthreads();
        float acc[4][4] = {};
        mm64(sCx, PL, sWb, PL, tr, tc, acc);
#pragma unroll
        for (int i = 0; i < 4; i++)
#pragma unroll
            for (int j = 0; j < 4; j++) {
                int row = tr + 16 * i, c = cc * 64 + tc * 4 + j;
                g_st[b * 16384 + row * 256 + c] = totf(acc[i][j] + bup[c]);
            }
    }
}

// ============================ K3: reader + channel mixer (tf32 mma) ============================
extern "C" __global__ void __launch_bounds__(256, 2)
k3(const float* __restrict__ xg,
   const float* __restrict__ g2, const float* __restrict__ b2,
   const float* __restrict__ binp, const float* __restrict__ boutp,
   float* __restrict__ out)
{
    extern __shared__ float sm[];
    float* sH  = sm;               // 64 x PH : LN2(y), tf32-rounded
    float* sWt = sH + 64 * PH;     // 64 x PL : w tile -> Win g-half -> act
    float* sWs = sWt + 64 * PL;    // 64 x PL : st chunk / Win v-half / Wout chunk
    float* sG2 = sWs + 64 * PL;    // 256
    float* sB2 = sG2 + 256;        // 256
    float* sBi = sB2 + 256;        // 128

    const int tid = threadIdx.x;
    const int warp = tid >> 5, lane = tid & 31;
    const int wr = warp >> 1, wc = warp & 1;      // 4x2 warp grid
    const int g = lane >> 2, q = lane & 3;
    const int b = blockIdx.x / BPB, rb = blockIdx.x % BPB;

    sG2[tid] = g2[tid]; sB2[tid] = b2[tid];
    if (tid < 128) sBi[tid] = binp[tid];
    __syncthreads();

    for (int tile = rb; tile < NTILE; tile += BPB) {
        const size_t tok0 = (size_t)b * NTOK + (size_t)tile * TT;
        __syncthreads();   // previous tile readers done

        // w tile (already tf32) -> sWt
        for (int i = tid; i < 64 * 64; i += 256) {
            int t = i >> 6, s = i & 63;
            sWt[t * PL + s] = g_w[(tok0 + t) * SD + s];
        }

        // GEMM A: y = x + w@st, per 64-col chunk
        for (int cc = 0; cc < 4; cc++) {
            __syncthreads();
            stage64c(sWs, g_st + b * 16384 + cc * 64, 256, tid);
            __syncthreads();
            float acc[4][4] = {};
            mma_warp64(sWt, PL, sWs, wr, wc, g, q, acc);
#pragma unroll
            for (int t = 0; t < 4; t++) {
                int col = cc * 64 + wc * 32 + t * 8 + 2 * q;
                size_t r0 = (tok0 + wr * 16 + g) * CD + col;
                size_t r1 = r0 + 8 * CD;
                float2 x0 = *reinterpret_cast<const float2*>(xg + r0);
                float2 x1 = *reinterpret_cast<const float2*>(xg + r1);
                *reinterpret_cast<float2*>(out + r0) = make_float2(acc[t][0] + x0.x, acc[t][1] + x0.y);
                *reinterpret_cast<float2*>(out + r1) = make_float2(acc[t][2] + x1.x, acc[t][3] + x1.y);
            }
        }
        __syncthreads();   // all y visible to block

        // LN2: y (from out) -> h (tf32-rounded) in sH
#pragma unroll 1
        for (int qq = 0; qq < 8; qq++) {
            int t = warp * 8 + qq;
            const float* yrow = out + (tok0 + t) * CD;
            float v[8], s1 = 0.0f, s2 = 0.0f;
#pragma unroll
            for (int k = 0; k < 8; k++) { v[k] = yrow[lane + 32 * k]; s1 += v[k]; s2 += v[k] * v[k]; }
#pragma unroll
            for (int o = 16; o > 0; o >>= 1) {
                s1 += __shfl_xor_sync(~0u, s1, o);
                s2 += __shfl_xor_sync(~0u, s2, o);
            }
            float m = s1 * (1.0f / 256.0f);
            float r = rsqrtf(fmaxf(s2 * (1.0f / 256.0f) - m * m, 0.0f) + 1e-5f);
#pragma unroll
            for (int k = 0; k < 8; k++) {
                int c = lane + 32 * k;
                sH[t * PH + c] = totf((v[k] - m) * r * sG2[c] + sB2[c]);
            }
        }

        // GEMM B: vg = h @ Win (both halves, accumulators in regs)
        float accv[4][4] = {}, accg[4][4] = {};
        for (int kt = 0; kt < 4; kt++) {
            __syncthreads();   // kt=0: sH visible + sWt/sWs reads done
            stage64c(sWs, g_WinT + kt * 64 * 128, 128, tid);
            stage64c(sWt, g_WinT + kt * 64 * 128 + 64, 128, tid);
            __syncthreads();
            mma_warp64(sH + kt * 64, PH, sWs, wr, wc, g, q, accv);
            mma_warp64(sH + kt * 64, PH, sWt, wr, wc, g, q, accg);
        }
        __syncthreads();   // mma reads of sWt done before act store

        // act = gelu(v)*sigmoid(g) -> sWt (tf32)
#pragma unroll
        for (int t = 0; t < 4; t++) {
            int col = wc * 32 + t * 8 + 2 * q;
            int s0 = (wr * 16 + g) * PL + col;
            int s1 = s0 + 8 * PL;
            sWt[s0]     = totf(geluf(accv[t][0] + sBi[col])     * sigm(accg[t][0] + sBi[64 + col]));
            sWt[s0 + 1] = totf(geluf(accv[t][1] + sBi[col + 1]) * sigm(accg[t][1] + sBi[64 + col + 1]));
            sWt[s1]     = totf(geluf(accv[t][2] + sBi[col])     * sigm(accg[t][2] + sBi[64 + col]));
            sWt[s1 + 1] = totf(geluf(accv[t][3] + sBi[col + 1]) * sigm(accg[t][3] + sBi[64 + col + 1]));
        }

        // GEMM C: out = y + act @ Wout + bout
        for (int cc = 0; cc < 4; cc++) {
            __syncthreads();   // cc=0: act visible; cc>0: prev sWs reads done
            stage64c(sWs, g_WoutT + cc * 64, 256, tid);
            __syncthreads();
            float acc[4][4] = {};
            mma_warp64(sWt, PL, sWs, wr, wc, g, q, acc);
#pragma unroll
            for (int t = 0; t < 4; t++) {
                int col = cc * 64 + wc * 32 + t * 8 + 2 * q;
                size_t r0 = (tok0 + wr * 16 + g) * CD + col;
                size_t r1 = r0 + 8 * CD;
                float2 y0 = *reinterpret_cast<const float2*>(out + r0);
                float2 y1 = *reinterpret_cast<const float2*>(out + r1);
                float2 bo = *reinterpret_cast<const float2*>(boutp + col);
                *reinterpret_cast<float2*>(out + r0) =
                    make_float2(y0.x + acc[t][0] + bo.x, y0.y + acc[t][1] + bo.y);
                *reinterpret_cast<float2*>(out + r1) =
                    make_float2(y1.x + acc[t][2] + bo.x, y1.y + acc[t][3] + bo.y);
            }
        }
    }
}

// ============================ launcher ============================
extern "C" void kernel_launch(void* const* d_in, const int* in_sizes, int n_in,
                              void* d_out, int out_size)
{
    const float* x     = (const float*)d_in[0];
    const float* geo   = (const float*)d_in[1];
    const float* ln1g  = (const float*)d_in[2];
    const float* ln1b  = (const float*)d_in[3];
    const float* Wsh   = (const float*)d_in[4];
    const float* bsh   = (const float*)d_in[5];
    const float* Wfe   = (const float*)d_in[6];
    const float* bfe   = (const float*)d_in[7];
    const float* Wasn  = (const float*)d_in[8];
    const float* basn  = (const float*)d_in[9];
    const float* Wd    = (const float*)d_in[10];
    const float* bd    = (const float*)d_in[11];
    const float* gdn   = (const float*)d_in[12];
    const float* bdn   = (const float*)d_in[13];
    const float* Wanc  = (const float*)d_in[14];
    const float* banc  = (const float*)d_in[15];
    const float* Wself = (const float*)d_in[16];
    const float* Wctx  = (const float*)d_in[17];
    const float* gon   = (const float*)d_in[18];
    const float* bon   = (const float*)d_in[19];
    const float* Wup   = (const float*)d_in[20];
    const float* bup   = (const float*)d_in[21];
    const float* ln2g  = (const float*)d_in[22];
    const float* ln2b  = (const float*)d_in[23];
    const float* Win   = (const float*)d_in[24];
    const float* binp  = (const float*)d_in[25];
    const float* Wout  = (const float*)d_in[26];
    const float* boutp = (const float*)d_in[27];
    float* out = (float*)d_out;

    const size_t S1 = (size_t)(5 * 64 * PL + 2 * 256 + 4 * 64) * sizeof(float);
    const size_t S2 = (size_t)(64 * PH + 256 * PL + 3 * 64 * PL + 16 * PL + 64 * 20 + 16 + 64) * sizeof(float);
    const size_t S3 = (size_t)(64 * PH + 2 * 64 * PL + 2 * 256 + 128) * sizeof(float);

    cudaFuncSetAttribute(k1, cudaFuncAttributeMaxDynamicSharedMemorySize, (int)S1);
    cudaFuncSetAttribute(k2, cudaFuncAttributeMaxDynamicSharedMemorySize, (int)S2);
    cudaFuncSetAttribute(k3, cudaFuncAttributeMaxDynamicSharedMemorySize, (int)S3);

    void* pM = nullptr; void* pwsum = nullptr;
    cudaGetSymbolAddress(&pM, g_M);
    cudaGetSymbolAddress(&pwsum, g_wsum);
    cudaMemsetAsync(pM, 0, (size_t)NB * SD * LD * sizeof(float), 0);
    cudaMemsetAsync(pwsum, 0, (size_t)NB * SD * sizeof(float), 0);

    k0<<<128, 256>>>(Win, Wout);
    k1<<<NB * BPB, 256, S1>>>(x, geo, ln1g, ln1b, Wsh, bsh, Wasn, basn);
    k2<<<NB, 256, S2>>>(Wfe, bfe, Wd, bd, gdn, bdn, Wanc, banc, Wself, Wctx, gon, bon, Wup, bup);
    k3<<<NB * BPB, 256, S3>>>(x, ln2g, ln2b, binp, boutp, out);
}

// round 11
// speedup vs baseline: 1.7014x; 1.1005x over previous
#include <cuda_runtime.h>
#include <math.h>

#define NB   4
#define NTOK 65536
#define CD   256
#define LD   64
#define SD   64
#define TT   64
#define BPB  74
#define NTILE 1024
#define PH 260
#define PL 68

__device__ float g_w[(size_t)NB * NTOK * SD];   // softmax weights (tf32-rounded)
__device__ float g_M[NB * SD * LD];             // accumulated w^T @ shared
__device__ float g_wsum[NB * SD];
__device__ float g_st[NB * SD * CD];            // st (tf32-rounded)
__device__ float g_WinT[CD * 128];              // tf32-rounded Win
__device__ float g_WoutT[LD * CD];              // tf32-rounded Wout

__device__ __forceinline__ float geluf(float x) {
    return 0.5f * x * (1.0f + erff(x * 0.70710678118654752f));
}
__device__ __forceinline__ float sigm(float x) { return 1.0f / (1.0f + __expf(-x)); }

__device__ __forceinline__ float totf(float x) {
    unsigned r;
    asm("cvt.rna.tf32.f32 %0, %1;" : "=r"(r) : "f"(x));
    return __uint_as_float(r);
}

__device__ __forceinline__ void mma8(float (&d)[4], const unsigned (&a)[4], const unsigned (&b)[2]) {
    asm volatile("mma.sync.aligned.m16n8k8.row.col.f32.tf32.tf32.f32 "
                 "{%0,%1,%2,%3}, {%4,%5,%6,%7}, {%8,%9}, {%0,%1,%2,%3};"
                 : "+f"(d[0]), "+f"(d[1]), "+f"(d[2]), "+f"(d[3])
                 : "r"(a[0]), "r"(a[1]), "r"(a[2]), "r"(a[3]), "r"(b[0]), "r"(b[1]));
}

// warp-level: acc(16x32) += A(64 rows, K=64 slice, lda) @ B(64x64 chunk, ld 68).
// warp tile: rows wr*16.., cols wc*32 + 8t. Operands must be tf32-rounded.
__device__ __forceinline__ void mma_warp64(const float* __restrict__ sA, int lda,
                                           const float* __restrict__ sB,
                                           int wr, int wc, int g, int q, float (&acc)[4][4])
{
#pragma unroll
    for (int k8 = 0; k8 < 64; k8 += 8) {
        const float* Ab = sA + (wr * 16 + g) * lda + k8 + q;
        unsigned a[4] = { __float_as_uint(Ab[0]),  __float_as_uint(Ab[8 * lda]),
                          __float_as_uint(Ab[4]),  __float_as_uint(Ab[8 * lda + 4]) };
#pragma unroll
        for (int t = 0; t < 4; t++) {
            const float* Bb = sB + (k8 + q) * PL + wc * 32 + t * 8 + g;
            unsigned b[2] = { __float_as_uint(Bb[0]), __float_as_uint(Bb[4 * PL]) };
            mma8(acc[t], a, b);
        }
    }
}

// ---------- scalar micro-kernels (k2 + k1's GEMM4') ----------
__device__ __forceinline__ void mm64(const float* __restrict__ A, int ald,
                                     const float* __restrict__ B, int bld,
                                     int tr, int tc, float (&acc)[4][4])
{
#pragma unroll 8
    for (int kk = 0; kk < 64; kk++) {
        float4 b4 = *reinterpret_cast<const float4*>(B + kk * bld + tc * 4);
        float a[4] = { A[tr * ald + kk], A[(tr + 16) * ald + kk],
                       A[(tr + 32) * ald + kk], A[(tr + 48) * ald + kk] };
        float bb[4] = { b4.x, b4.y, b4.z, b4.w };
#pragma unroll
        for (int i = 0; i < 4; i++)
#pragma unroll
            for (int j = 0; j < 4; j++) acc[i][j] = fmaf(a[i], bb[j], acc[i][j]);
    }
}

__device__ __forceinline__ void mmT64(const float* __restrict__ A, int ald,
                                      const float* __restrict__ B, int bld,
                                      int tr, int tc, float (&acc)[4][4])
{
#pragma unroll 8
    for (int kk = 0; kk < 64; kk++) {
        float4 b4 = *reinterpret_cast<const float4*>(B + kk * bld + tc * 4);
        float a[4] = { A[kk * ald + tr], A[kk * ald + tr + 16],
                       A[kk * ald + tr + 32], A[kk * ald + tr + 48] };
        float bb[4] = { b4.x, b4.y, b4.z, b4.w };
#pragma unroll
        for (int i = 0; i < 4; i++)
#pragma unroll
            for (int j = 0; j < 4; j++) acc[i][j] = fmaf(a[i], bb[j], acc[i][j]);
    }
}

__device__ __forceinline__ void stage64c(float* dst, const float* __restrict__ src,
                                         int sld, int tid)
{
    for (int i = tid; i < 1024; i += 256) {
        int r = i >> 4, c4 = (i & 15) * 4;
        *reinterpret_cast<float4*>(dst + r * PL + c4) =
            *reinterpret_cast<const float4*>(src + r * sld + c4);
    }
}

// stage with tf32 rounding
__device__ __forceinline__ void stage64t(float* dst, const float* __restrict__ src,
                                         int sld, int tid)
{
    for (int i = tid; i < 1024; i += 256) {
        int r = i >> 4, c4 = (i & 15) * 4;
        float4 v = *reinterpret_cast<const float4*>(src + r * sld + c4);
        *reinterpret_cast<float4*>(dst + r * PL + c4) =
            make_float4(totf(v.x), totf(v.y), totf(v.z), totf(v.w));
    }
}

__device__ __forceinline__ void ln64(const float* src, float* dst,
                                     const float* __restrict__ gg, const float* __restrict__ bb,
                                     int warp, int lane)
{
#pragma unroll 1
    for (int q = 0; q < 8; q++) {
        int s = warp * 8 + q;
        float v0 = src[s * PL + lane], v1 = src[s * PL + lane + 32];
        float s1 = v0 + v1, s2 = v0 * v0 + v1 * v1;
#pragma unroll
        for (int o = 16; o > 0; o >>= 1) {
            s1 += __shfl_xor_sync(~0u, s1, o);
            s2 += __shfl_xor_sync(~0u, s2, o);
        }
        float m = s1 * (1.0f / 64.0f);
        float r = rsqrtf(fmaxf(s2 * (1.0f / 64.0f) - m * m, 0.0f) + 1e-5f);
        dst[s * PL + lane]      = (v0 - m) * r * gg[lane] + bb[lane];
        dst[s * PL + lane + 32] = (v1 - m) * r * gg[lane + 32] + bb[lane + 32];
    }
}

// ============================ K0: tf32-round the channel-mixer weights ============================
extern "C" __global__ void k0(const float* __restrict__ Win, const float* __restrict__ Wout)
{
    int i = blockIdx.x * 256 + threadIdx.x;
    if (i < CD * 128) g_WinT[i] = totf(Win[i]);
    if (i < LD * CD)  g_WoutT[i] = totf(Wout[i]);
}

// ============================ K1: phase 1 (tf32 mma GEMM1+GEMM3) ============================
extern "C" __global__ void __launch_bounds__(256, 2)
k1(const float* __restrict__ xg, const float* __restrict__ geo,
   const float* __restrict__ g1, const float* __restrict__ b1,
   const float* __restrict__ Wsh, const float* __restrict__ bsh,
   const float* __restrict__ Wasn, const float* __restrict__ basn)
{
    extern __shared__ float sm[];
    float* sX   = sm;                 // 64 x PL  (normalized x chunk, tf32)
    float* sSh  = sX + 64 * PL;       // 64 x PL  (shared, tf32-rounded)
    float* sLg  = sSh + 64 * PL;      // 64 x PL  (logits -> w)
    float* sGeo = sLg + 64 * PL;      // 64 x PL  (geo, tf32)
    float* sW   = sGeo + 64 * PL;     // 64 x PL  (weight stage, tf32)
    float* sG1  = sW + 64 * PL;       // 256
    float* sB1  = sG1 + 256;          // 256
    float* sMean = sB1 + 256;         // 64
    float* sRstd = sMean + 64;        // 64
    float* sBsh = sRstd + 64;         // 64
    float* sBa  = sBsh + 64;          // 64

    const int tid = threadIdx.x;
    const int tr = tid >> 4, tc = tid & 15;
    const int warp = tid >> 5, lane = tid & 31;
    const int wr = warp >> 1, wc = warp & 1;      // 4x2 warp grid for mma
    const int g = lane >> 2, q = lane & 3;
    const int b = blockIdx.x / BPB, rb = blockIdx.x % BPB;

    sG1[tid] = g1[tid]; sB1[tid] = b1[tid];
    if (tid < 64) { sBsh[tid] = bsh[tid]; sBa[tid] = basn[tid]; }
    float wloc = 0.0f;
    float Macc[4][4] = {};
    __syncthreads();

    for (int tile = rb; tile < NTILE; tile += BPB) {
        const size_t tok0 = (size_t)b * NTOK + (size_t)tile * TT;
        __syncthreads();   // prev tile readers (softmax, mmT64 on sLg/sSh/sGeo) done

        // LN stats
#pragma unroll 1
        for (int qq = 0; qq < 8; qq++) {
            int t = warp * 8 + qq;
            const float* row = xg + (tok0 + t) * CD;
            float s1 = 0.0f, s2 = 0.0f;
#pragma unroll
            for (int k = 0; k < 8; k++) { float v = row[lane + 32 * k]; s1 += v; s2 += v * v; }
#pragma unroll
            for (int o = 16; o > 0; o >>= 1) {
                s1 += __shfl_xor_sync(~0u, s1, o);
                s2 += __shfl_xor_sync(~0u, s2, o);
            }
            if (lane == 0) {
                float m = s1 * (1.0f / 256.0f);
                sMean[t] = m;
                sRstd[t] = rsqrtf(fmaxf(s2 * (1.0f / 256.0f) - m * m, 0.0f) + 1e-5f);
            }
        }
        // geo -> sGeo (tf32)
        for (int i = tid; i < 1024; i += 256) {
            int t = i >> 4, c4 = (i & 15) * 4;
            float4 v = *reinterpret_cast<const float4*>(geo + (tok0 + t) * LD + c4);
            *reinterpret_cast<float4*>(sGeo + t * PL + c4) =
                make_float4(totf(v.x), totf(v.y), totf(v.z), totf(v.w));
        }

        // GEMM1 (mma): shared = LN(x) @ Wsh   (K=256, 4 chunks)
        float a1[4][4] = {};
        for (int kt = 0; kt < 4; kt++) {
            __syncthreads();   // kt=0: stats visible, sX/sW free; kt>0: prev mma done
            const int base = kt * 64;
#pragma unroll
            for (int ii = 0; ii < 4; ii++) {
                int idx = tid + ii * 256;
                int r = idx >> 4, c4 = (idx & 15) * 4;
                float4 xv = *reinterpret_cast<const float4*>(xg + (tok0 + r) * CD + base + c4);
                float m = sMean[r], rs = sRstd[r];
                *reinterpret_cast<float4*>(sX + r * PL + c4) = make_float4(
                    totf((xv.x - m) * rs * sG1[base + c4 + 0] + sB1[base + c4 + 0]),
                    totf((xv.y - m) * rs * sG1[base + c4 + 1] + sB1[base + c4 + 1]),
                    totf((xv.z - m) * rs * sG1[base + c4 + 2] + sB1[base + c4 + 2]),
                    totf((xv.w - m) * rs * sG1[base + c4 + 3] + sB1[base + c4 + 3]));
            }
            stage64t(sW, Wsh + base * 64, 64, tid);
            __syncthreads();
            mma_warp64(sX, PL, sW, wr, wc, g, q, a1);
        }
        __syncthreads();   // mma done; sW free; sSh writable
        // store shared (tf32-rounded, +bias) from fragments
#pragma unroll
        for (int t = 0; t < 4; t++) {
            int col = wc * 32 + t * 8 + 2 * q;
            int r0 = (wr * 16 + g) * PL, r1 = r0 + 8 * PL;
            sSh[r0 + col]     = totf(a1[t][0] + sBsh[col]);
            sSh[r0 + col + 1] = totf(a1[t][1] + sBsh[col + 1]);
            sSh[r1 + col]     = totf(a1[t][2] + sBsh[col]);
            sSh[r1 + col + 1] = totf(a1[t][3] + sBsh[col + 1]);
        }
        stage64t(sW, Wasn, 64, tid);
        __syncthreads();   // sSh + sW visible

        // GEMM3 (mma): logits = shared@Wasn0 + geo@Wasn1
        float a3[4][4] = {};
        mma_warp64(sSh, PL, sW, wr, wc, g, q, a3);
        __syncthreads();
        stage64t(sW, Wasn + 64 * 64, 64, tid);
        __syncthreads();
        mma_warp64(sGeo, PL, sW, wr, wc, g, q, a3);
#pragma unroll
        for (int t = 0; t < 4; t++) {
            int col = wc * 32 + t * 8 + 2 * q;
            int r0 = (wr * 16 + g) * PL, r1 = r0 + 8 * PL;
            sLg[r0 + col]     = a3[t][0] + sBa[col];
            sLg[r0 + col + 1] = a3[t][1] + sBa[col + 1];
            sLg[r1 + col]     = a3[t][2] + sBa[col];
            sLg[r1 + col + 1] = a3[t][3] + sBa[col + 1];
        }
        __syncthreads();

        // softmax -> w (fp32 in sLg; tf32 spill for k3)
#pragma unroll 1
        for (int qq = 0; qq < 8; qq++) {
            int t = warp * 8 + qq;
            float v0 = sLg[t * PL + lane], v1 = sLg[t * PL + lane + 32];
            float mx = fmaxf(v0, v1);
#pragma unroll
            for (int o = 16; o > 0; o >>= 1) mx = fmaxf(mx, __shfl_xor_sync(~0u, mx, o));
            float e0 = __expf(v0 - mx), e1 = __expf(v1 - mx), ss = e0 + e1;
#pragma unroll
            for (int o = 16; o > 0; o >>= 1) ss += __shfl_xor_sync(~0u, ss, o);
            float inv = 1.0f / ss;
            float w0 = e0 * inv, w1 = e1 * inv;
            sLg[t * PL + lane] = w0; sLg[t * PL + lane + 32] = w1;
            float* wo = g_w + (tok0 + t) * SD;
            wo[lane] = totf(w0); wo[lane + 32] = totf(w1);
        }
        __syncthreads();

        if (tid < 64) {
            float cs = 0.0f;
            for (int t = 0; t < 64; t++) cs += sLg[t * PL + tid];
            wloc += cs;
        }
        // GEMM4': Macc += w^T @ shared (scalar fp32, register resident)
        mmT64(sLg, PL, sSh, PL, tr, tc, Macc);
    }

    if (tid < 64) atomicAdd(&g_wsum[b * 64 + tid], wloc);
#pragma unroll
    for (int i = 0; i < 4; i++)
#pragma unroll
        for (int j = 0; j < 4; j++)
            atomicAdd(&g_M[b * 4096 + (tr + 16 * i) * 64 + tc * 4 + j], Macc[i][j]);
}

// ============================ K2: slice reconstruction + latent transition ============================
extern "C" __global__ void __launch_bounds__(256, 1)
k2(const float* __restrict__ Wfe, const float* __restrict__ bfe,
   const float* __restrict__ Wd, const float* __restrict__ bd,
   const float* __restrict__ gdn, const float* __restrict__ bdn,
   const float* __restrict__ Wanc, const float* __restrict__ banc,
   const float* __restrict__ Wself, const float* __restrict__ Wctx,
   const float* __restrict__ gon, const float* __restrict__ bon,
   const float* __restrict__ Wup, const float* __restrict__ bup)
{
    extern __shared__ float sm[];
    float* sS  = sm;               // 64 x PH
    float* sWb = sS + 64 * PH;     // 256 x PL
    float* sT1 = sWb + 256 * PL;   // 64 x PL
    float* sT2 = sT1 + 64 * PL;    // 64 x PL
    float* sCx = sT2 + 64 * PL;    // 64 x PL
    float* sAn = sCx + 64 * PL;    // 16 x PL
    float* sAw = sAn + 16 * PL;    // 64 x 20
    float* sAs = sAw + 64 * 20;    // 16
    float* sWm = sAs + 16;         // 64

    const int tid = threadIdx.x;
    const int tr = tid >> 4, tc = tid & 15;
    const int warp = tid >> 5, lane = tid & 31;
    const int b = blockIdx.x;

    if (tid < 64) sWm[tid] = fmaxf(g_wsum[b * 64 + tid], 1e-6f);
    for (int i = tid; i < 64 * 64; i += 256) {
        int s = i >> 6, l = i & 63;
        sT1[s * PL + l] = g_M[b * 4096 + i];
    }
    __syncthreads();

    for (int cc = 0; cc < 4; cc++) {
        __syncthreads();
        stage64c(sWb, Wfe + cc * 64, 256, tid);
        __syncthreads();
        float acc[4][4] = {};
        mm64(sT1, PL, sWb, PL, tr, tc, acc);
#pragma unroll
        for (int i = 0; i < 4; i++)
#pragma unroll
            for (int j = 0; j < 4; j++) {
                int s = tr + 16 * i, c = cc * 64 + tc * 4 + j;
                float ws = sWm[s];
                sS[s * PH + c] = (acc[i][j] + ws * bfe[c]) / ws;
            }
    }
    __syncthreads();

    for (int i = tid; i < 256 * 16; i += 256) {
        int r = i >> 4, c4 = (i & 15) * 4;
        *reinterpret_cast<float4*>(sWb + r * PL + c4) =
            *reinterpret_cast<const float4*>(Wd + r * 64 + c4);
    }
    __syncthreads();
    {
        float acc[4][4] = {};
        for (int kt = 0; kt < 4; kt++)
            mm64(sS + kt * 64, PH, sWb + kt * 64 * PL, PL, tr, tc, acc);
        __syncthreads();
#pragma unroll
        for (int i = 0; i < 4; i++)
#pragma unroll
            for (int j = 0; j < 4; j++) {
                int c = tc * 4 + j;
                sT2[(tr + 16 * i) * PL + c] = acc[i][j] + bd[c];
            }
    }
    __syncthreads();
    ln64(sT2, sT1, gdn, bdn, warp, lane);
    __syncthreads();

    {
        int s = tid >> 2, a0 = (tid & 3) * 4;
        float a4[4] = {0.f, 0.f, 0.f, 0.f};
        for (int k = 0; k < 64; k++) {
            float av = sT1[s * PL + k];
#pragma unroll
            for (int j = 0; j < 4; j++) a4[j] = fmaf(av, Wanc[k * 16 + a0 + j], a4[j]);
        }
#pragma unroll
        for (int j = 0; j < 4; j++) sAw[s * 20 + a0 + j] = a4[j] + banc[a0 + j];
    }
    __syncthreads();
    if (tid < 64) {
        float mx = -1e30f;
        for (int a = 0; a < 16; a++) mx = fmaxf(mx, sAw[tid * 20 + a]);
        float e[16], ss = 0.0f;
        for (int a = 0; a < 16; a++) { e[a] = __expf(sAw[tid * 20 + a] - mx); ss += e[a]; }
        float inv = 1.0f / ss;
        for (int a = 0; a < 16; a++) sAw[tid * 20 + a] = e[a] * inv;
    }
    __syncthreads();
    if (tid < 16) {
        float cs = 0.0f;
        for (int s = 0; s < 64; s++) cs += sAw[s * 20 + tid];
        sAs[tid] = fmaxf(cs, 1e-6f);
    }
    __syncthreads();
    for (int idx = tid; idx < 16 * 64; idx += 256) {
        int a = idx >> 6, d = idx & 63;
        float s = 0.0f;
        for (int t = 0; t < 64; t++) s = fmaf(sAw[t * 20 + a], sT1[t * PL + d], s);
        sAn[a * PL + d] = s / sAs[a];
    }
    __syncthreads();
    for (int idx = tid; idx < 64 * 64; idx += 256) {
        int s = idx >> 6, d = idx & 63;
        float v = 0.0f;
#pragma unroll
        for (int a = 0; a < 16; a++) v = fmaf(sAw[s * 20 + a], sAn[a * PL + d], v);
        sCx[s * PL + d] = v;
    }
    __syncthreads();

    {
        float acc[4][4] = {};
        for (int i = tid; i < 64 * 16; i += 256) {
            int r = i >> 4, c4 = (i & 15) * 4;
            *reinterpret_cast<float4*>(sWb + r * PL + c4) =
                *reinterpret_cast<const float4*>(Wself + r * 64 + c4);
        }
        __syncthreads();
        mm64(sT1, PL, sWb, PL, tr, tc, acc);
        __syncthreads();
        for (int i = tid; i < 64 * 16; i += 256) {
            int r = i >> 4, c4 = (i & 15) * 4;
            *reinterpret_cast<float4*>(sWb + r * PL + c4) =
                *reinterpret_cast<const float4*>(Wctx + r * 64 + c4);
        }
        __syncthreads();
        mm64(sCx, PL, sWb, PL, tr, tc, acc);
#pragma unroll
        for (int i = 0; i < 4; i++)
#pragma unroll
            for (int j = 0; j < 4; j++) {
                int row = tr + 16 * i, c = tc * 4 + j;
                sT2[row * PL + c] = sT1[row * PL + c] + geluf(acc[i][j]);
            }
    }
    __syncthreads();
    ln64(sT2, sCx, gon, bon, warp, lane);
    __syncthreads();

    // st = LN(ul)@Wup + bup  (stored tf32-rounded for k3 mma)
    for (int cc = 0; cc < 4; cc++) {
        __syncthreads();
        for (int i = tid; i < 64 * 16; i += 256) {
            int r = i >> 4, c4 = (i & 15) * 4;
            *reinterpret_cast<float4*>(sWb + r * PL + c4) =
                *reinterpret_cast<const float4*>(Wup + r * 256 + cc * 64 + c4);
        }
        __syncthreads();
        float acc[4][4] = {};
        mm64(sCx, PL, sWb, PL, tr, tc, acc);
#pragma unroll
        for (int i = 0; i < 4; i++)
#pragma unroll
            for (int j = 0; j < 4; j++) {
                int row = tr + 16 * i, c = cc * 64 + tc * 4 + j;
                g_st[b * 16384 + row * 256 + c] = totf(acc[i][j] + bup[c]);
            }
    }
}

// ============================ K3: reader + channel mixer (tf32 mma) ============================
extern "C" __global__ void __launch_bounds__(256, 2)
k3(const float* __restrict__ xg,
   const float* __restrict__ g2, const float* __restrict__ b2,
   const float* __restrict__ binp, const float* __restrict__ boutp,
   float* __restrict__ out)
{
    extern __shared__ float sm[];
    float* sH  = sm;               // 64 x PH : LN2(y), tf32-rounded
    float* sWt = sH + 64 * PH;     // 64 x PL : w tile -> Win g-half -> act
    float* sWs = sWt + 64 * PL;    // 64 x PL : st chunk / Win v-half / Wout chunk
    float* sG2 = sWs + 64 * PL;    // 256
    float* sB2 = sG2 + 256;        // 256
    float* sBi = sB2 + 256;        // 128

    const int tid = threadIdx.x;
    const int warp = tid >> 5, lane = tid & 31;
    const int wr = warp >> 1, wc = warp & 1;
    const int g = lane >> 2, q = lane & 3;
    const int b = blockIdx.x / BPB, rb = blockIdx.x % BPB;

    sG2[tid] = g2[tid]; sB2[tid] = b2[tid];
    if (tid < 128) sBi[tid] = binp[tid];
    __syncthreads();

    for (int tile = rb; tile < NTILE; tile += BPB) {
        const size_t tok0 = (size_t)b * NTOK + (size_t)tile * TT;
        __syncthreads();

        // w tile (already tf32) -> sWt (vectorized)
        for (int i = tid; i < 1024; i += 256) {
            int t = i >> 4, c4 = (i & 15) * 4;
            *reinterpret_cast<float4*>(sWt + t * PL + c4) =
                *reinterpret_cast<const float4*>(g_w + (tok0 + t) * SD + c4);
        }

        // GEMM A: y = x + w@st
        for (int cc = 0; cc < 4; cc++) {
            __syncthreads();
            stage64c(sWs, g_st + b * 16384 + cc * 64, 256, tid);
            __syncthreads();
            float acc[4][4] = {};
            mma_warp64(sWt, PL, sWs, wr, wc, g, q, acc);
#pragma unroll
            for (int t = 0; t < 4; t++) {
                int col = cc * 64 + wc * 32 + t * 8 + 2 * q;
                size_t r0 = (tok0 + wr * 16 + g) * CD + col;
                size_t r1 = r0 + 8 * CD;
                float2 x0 = *reinterpret_cast<const float2*>(xg + r0);
                float2 x1 = *reinterpret_cast<const float2*>(xg + r1);
                *reinterpret_cast<float2*>(out + r0) = make_float2(acc[t][0] + x0.x, acc[t][1] + x0.y);
                *reinterpret_cast<float2*>(out + r1) = make_float2(acc[t][2] + x1.x, acc[t][3] + x1.y);
            }
        }
        __syncthreads();

        // LN2: y (from out) -> h (tf32) in sH
#pragma unroll 1
        for (int qq = 0; qq < 8; qq++) {
            int t = warp * 8 + qq;
            const float* yrow = out + (tok0 + t) * CD;
            float v[8], s1 = 0.0f, s2 = 0.0f;
#pragma unroll
            for (int k = 0; k < 8; k++) { v[k] = yrow[lane + 32 * k]; s1 += v[k]; s2 += v[k] * v[k]; }
#pragma unroll
            for (int o = 16; o > 0; o >>= 1) {
                s1 += __shfl_xor_sync(~0u, s1, o);
                s2 += __shfl_xor_sync(~0u, s2, o);
            }
            float m = s1 * (1.0f / 256.0f);
            float r = rsqrtf(fmaxf(s2 * (1.0f / 256.0f) - m * m, 0.0f) + 1e-5f);
#pragma unroll
            for (int k = 0; k < 8; k++) {
                int c = lane + 32 * k;
                sH[t * PH + c] = totf((v[k] - m) * r * sG2[c] + sB2[c]);
            }
        }

        // GEMM B: vg = h @ Win
        float accv[4][4] = {}, accg[4][4] = {};
        for (int kt = 0; kt < 4; kt++) {
            __syncthreads();
            stage64c(sWs, g_WinT + kt * 64 * 128, 128, tid);
            stage64c(sWt, g_WinT + kt * 64 * 128 + 64, 128, tid);
            __syncthreads();
            mma_warp64(sH + kt * 64, PH, sWs, wr, wc, g, q, accv);
            mma_warp64(sH + kt * 64, PH, sWt, wr, wc, g, q, accg);
        }
        __syncthreads();

        // act -> sWt (tf32)
#pragma unroll
        for (int t = 0; t < 4; t++) {
            int col = wc * 32 + t * 8 + 2 * q;
            int s0 = (wr * 16 + g) * PL + col;
            int s1 = s0 + 8 * PL;
            sWt[s0]     = totf(geluf(accv[t][0] + sBi[col])     * sigm(accg[t][0] + sBi[64 + col]));
            sWt[s0 + 1] = totf(geluf(accv[t][1] + sBi[col + 1]) * sigm(accg[t][1] + sBi[64 + col + 1]));
            sWt[s1]     = totf(geluf(accv[t][2] + sBi[col])     * sigm(accg[t][2] + sBi[64 + col]));
            sWt[s1 + 1] = totf(geluf(accv[t][3] + sBi[col + 1]) * sigm(accg[t][3] + sBi[64 + col + 1]));
        }

        // GEMM C: out = y + act @ Wout + bout
        for (int cc = 0; cc < 4; cc++) {
            __syncthreads();
            stage64c(sWs, g_WoutT + cc * 64, 256, tid);
            __syncthreads();
            float acc[4][4] = {};
            mma_warp64(sWt, PL, sWs, wr, wc, g, q, acc);
#pragma unroll
            for (int t = 0; t < 4; t++) {
                int col = cc * 64 + wc * 32 + t * 8 + 2 * q;
                size_t r0 = (tok0 + wr * 16 + g) * CD + col;
                size_t r1 = r0 + 8 * CD;
                float2 y0 = *reinterpret_cast<const float2*>(out + r0);
                float2 y1 = *reinterpret_cast<const float2*>(out + r1);
                float2 bo = *reinterpret_cast<const float2*>(boutp + col);
                *reinterpret_cast<float2*>(out + r0) =
                    make_float2(y0.x + acc[t][0] + bo.x, y0.y + acc[t][1] + bo.y);
                *reinterpret_cast<float2*>(out + r1) =
                    make_float2(y1.x + acc[t][2] + bo.x, y1.y + acc[t][3] + bo.y);
            }
        }
    }
}

// ============================ launcher ============================
extern "C" void kernel_launch(void* const* d_in, const int* in_sizes, int n_in,
                              void* d_out, int out_size)
{
    const float* x     = (const float*)d_in[0];
    const float* geo   = (const float*)d_in[1];
    const float* ln1g  = (const float*)d_in[2];
    const float* ln1b  = (const float*)d_in[3];
    const float* Wsh   = (const float*)d_in[4];
    const float* bsh   = (const float*)d_in[5];
    const float* Wfe   = (const float*)d_in[6];
    const float* bfe   = (const float*)d_in[7];
    const float* Wasn  = (const float*)d_in[8];
    const float* basn  = (const float*)d_in[9];
    const float* Wd    = (const float*)d_in[10];
    const float* bd    = (const float*)d_in[11];
    const float* gdn   = (const float*)d_in[12];
    const float* bdn   = (const float*)d_in[13];
    const float* Wanc  = (const float*)d_in[14];
    const float* banc  = (const float*)d_in[15];
    const float* Wself = (const float*)d_in[16];
    const float* Wctx  = (const float*)d_in[17];
    const float* gon   = (const float*)d_in[18];
    const float* bon   = (const float*)d_in[19];
    const float* Wup   = (const float*)d_in[20];
    const float* bup   = (const float*)d_in[21];
    const float* ln2g  = (const float*)d_in[22];
    const float* ln2b  = (const float*)d_in[23];
    const float* Win   = (const float*)d_in[24];
    const float* binp  = (const float*)d_in[25];
    const float* Wout  = (const float*)d_in[26];
    const float* boutp = (const float*)d_in[27];
    float* out = (float*)d_out;

    const size_t S1 = (size_t)(5 * 64 * PL + 2 * 256 + 4 * 64) * sizeof(float);
    const size_t S2 = (size_t)(64 * PH + 256 * PL + 3 * 64 * PL + 16 * PL + 64 * 20 + 16 + 64) * sizeof(float);
    const size_t S3 = (size_t)(64 * PH + 2 * 64 * PL + 2 * 256 + 128) * sizeof(float);

    cudaFuncSetAttribute(k1, cudaFuncAttributeMaxDynamicSharedMemorySize, (int)S1);
    cudaFuncSetAttribute(k2, cudaFuncAttributeMaxDynamicSharedMemorySize, (int)S2);
    cudaFuncSetAttribute(k3, cudaFuncAttributeMaxDynamicSharedMemorySize, (int)S3);

    void* pM = nullptr; void* pwsum = nullptr;
    cudaGetSymbolAddress(&pM, g_M);
    cudaGetSymbolAddress(&pwsum, g_wsum);
    cudaMemsetAsync(pM, 0, (size_t)NB * SD * LD * sizeof(float), 0);
    cudaMemsetAsync(pwsum, 0, (size_t)NB * SD * sizeof(float), 0);

    k0<<<128, 256>>>(Win, Wout);
    k1<<<NB * BPB, 256, S1>>>(x, geo, ln1g, ln1b, Wsh, bsh, Wasn, basn);
    k2<<<NB, 256, S2>>>(Wfe, bfe, Wd, bd, gdn, bdn, Wanc, banc, Wself, Wctx, gon, bon, Wup, bup);
    k3<<<NB * BPB, 256, S3>>>(x, ln2g, ln2b, binp, boutp, out);
}